// round 8
// baseline (speedup 1.0000x reference)
#include <cuda_runtime.h>

// LossFunction: fused IoU + smooth-L1 multi-loss over (B=256, N=8192, F=13).
//
// R8: LDG.256 streaming (R6: 77.6% DRAM eff) + small in-flight footprint
// (R4: phase-2 L2 hits). THREADS=128, ROWS_TILE=1024 (1664 v8-chunks =
// 13*128 exact). 48KB static smem pad caps occupancy at 4 blocks/SM ->
// in-flight = 592 blocks * 104KB = 61MB < L2 (126MB), so each block's
// phase-2 row gathers hit L2. Latency covered by 26 batched LDG.256/thread.

#define F 13
#define THREADS 128
#define ROWS_TILE 1024
#define MAX_BLOCKS 4096

__device__ float        g_partials[MAX_BLOCKS];
__device__ unsigned int g_ticket = 0;

__device__ __forceinline__ float huber(float a, float b) {
    float d = fabsf(a - b);
    return d < 1.0f ? 0.5f * d * d : d - 0.5f;
}

__device__ __forceinline__ void ldg8(const float* p, float (&v)[8]) {
    unsigned r0, r1, r2, r3, r4, r5, r6, r7;
    asm("ld.global.nc.v8.b32 {%0,%1,%2,%3,%4,%5,%6,%7}, [%8];"
        : "=r"(r0), "=r"(r1), "=r"(r2), "=r"(r3),
          "=r"(r4), "=r"(r5), "=r"(r6), "=r"(r7)
        : "l"(p));
    v[0] = __uint_as_float(r0); v[1] = __uint_as_float(r1);
    v[2] = __uint_as_float(r2); v[3] = __uint_as_float(r3);
    v[4] = __uint_as_float(r4); v[5] = __uint_as_float(r5);
    v[6] = __uint_as_float(r6); v[7] = __uint_as_float(r7);
}

__global__ __launch_bounds__(THREADS)
void loss_kernel(const float* __restrict__ tg,
                 const float* __restrict__ pr,
                 float* __restrict__ out,
                 long long rows,
                 float c1, float cbase, float c2corr, float c3corr) {
    // Occupancy limiter: 48KB static smem -> floor(228KB/48KB) = 4 blocks/SM.
    // First few floats double as the reduction scratch.
    __shared__ float smem_pad[12288];  // 48 KB
    float* warp_part = smem_pad;       // THREADS/32 = 4 floats used
    __shared__ bool  is_last;

    long long row0 = (long long)blockIdx.x * ROWS_TILE;
    long long rem  = rows - row0;
    int nrows = rem < ROWS_TILE ? (int)rem : ROWS_TILE;

    const float* tbase = tg + row0 * F;
    const float* pbase = pr + row0 * F;

    // ---- Phase 1: uniform-weight streaming, LDG.256, no index math ----
    float a0 = 0.0f, a1 = 0.0f, a2 = 0.0f, a3 = 0.0f;

    if (nrows == ROWS_TILE) {
        int idx = threadIdx.x;                 // v8-chunk index
        #pragma unroll
        for (int k = 0; k < 13; k++) {         // 1024*13/8 = 13*THREADS exact
            float t[8], p[8];
            ldg8(tbase + idx * 8, t);
            ldg8(pbase + idx * 8, p);
            a0 += huber(t[0], p[0]) + huber(t[4], p[4]);
            a1 += huber(t[1], p[1]) + huber(t[5], p[5]);
            a2 += huber(t[2], p[2]) + huber(t[6], p[6]);
            a3 += huber(t[3], p[3]) + huber(t[7], p[7]);
            idx += THREADS;
        }
    } else {
        int nflt = nrows * F;
        for (int i = threadIdx.x; i < nflt; i += THREADS)
            a0 += huber(__ldg(tbase + i), __ldg(pbase + i));
    }
    float acc = (a0 + a1 + a2 + a3) * cbase;

    // ---- Phase 2: per-row corrections + IoU; tile is L2-hot (61MB in flight) ----
    for (int r = threadIdx.x; r < nrows; r += THREADS) {
        const float* tr = tbase + r * F;
        const float* pq = pbase + r * F;
        float t0 = __ldg(tr + 0), t1 = __ldg(tr + 1);
        float t2 = __ldg(tr + 2), t3 = __ldg(tr + 3);
        float t12 = __ldg(tr + 12);
        float p0 = __ldg(pq + 0), p1 = __ldg(pq + 1);
        float p2 = __ldg(pq + 2), p3 = __ldg(pq + 3);
        float p12 = __ldg(pq + 12);

        float s2 = huber(t0, p0) + huber(t1, p1) + huber(t2, p2) + huber(t3, p3);
        acc += c2corr * s2;
        acc += c3corr * huber(t12, p12);

        float xx1 = fmaxf(t0, p0);
        float yy1 = fmaxf(t1, p1);
        float xx2 = fminf(t2, p2);
        float yy2 = fminf(t3, p3);
        float w = fmaxf(xx2 - xx1, 0.0f);
        float h = fmaxf(yy2 - yy1, 0.0f);
        float inter = w * h;
        float area1 = (t2 - t0) * (t3 - t1);
        float area2 = (p2 - p0) * (p3 - p1);
        float iou = inter / (area1 + area2 - inter + 1e-7f);
        acc += c1 * huber(1.0f, iou);
    }

    // ---- Block reduction ----
    #pragma unroll
    for (int off = 16; off > 0; off >>= 1)
        acc += __shfl_xor_sync(0xFFFFFFFFu, acc, off);

    int lane = threadIdx.x & 31;
    int wid  = threadIdx.x >> 5;
    if (lane == 0) warp_part[wid] = acc;
    __syncthreads();

    if (wid == 0) {
        float v = lane < (THREADS / 32) ? warp_part[lane] : 0.0f;
        #pragma unroll
        for (int off = 2; off > 0; off >>= 1)
            v += __shfl_xor_sync(0xFFFFFFFFu, v, off);
        if (lane == 0) {
            g_partials[blockIdx.x] = v;
            __threadfence();
            unsigned t = atomicAdd(&g_ticket, 1u);
            is_last = (t == gridDim.x - 1);
        }
    }
    __syncthreads();

    // Last block reduces all partials (deterministic order) and writes out.
    if (is_last) {
        __threadfence();
        float v = 0.0f;
        for (int i = threadIdx.x; i < (int)gridDim.x; i += THREADS)
            v += g_partials[i];
        #pragma unroll
        for (int off = 16; off > 0; off >>= 1)
            v += __shfl_xor_sync(0xFFFFFFFFu, v, off);
        if (lane == 0) warp_part[wid] = v;
        __syncthreads();
        if (wid == 0) {
            float s = lane < (THREADS / 32) ? warp_part[lane] : 0.0f;
            #pragma unroll
            for (int off = 2; off > 0; off >>= 1)
                s += __shfl_xor_sync(0xFFFFFFFFu, s, off);
            if (lane == 0) {
                out[0] = s;
                g_ticket = 0;   // reset for next graph replay
            }
        }
    }
}

extern "C" void kernel_launch(void* const* d_in, const int* in_sizes, int n_in,
                              void* d_out, int out_size) {
    const float* targets = (const float*)d_in[0];
    const float* preds   = (const float*)d_in[1];
    float* out = (float*)d_out;

    long long total = (long long)in_sizes[0];
    long long rows  = total / F;  // B*N = 2,097,152

    float inv = 1.0f / (float)rows;
    // Per-element weights: f<4: inv/4; 4<=f<12: inv/16; f==12: inv.
    float cbase  = inv * 0.0625f;
    float c2corr = inv * 0.25f - cbase;
    float c3corr = inv - cbase;
    float c1     = inv;

    int grid = (int)((rows + ROWS_TILE - 1) / ROWS_TILE);  // 2048
    if (grid > MAX_BLOCKS) grid = MAX_BLOCKS;  // safety (not hit for bench shape)

    loss_kernel<<<grid, THREADS>>>(targets, preds, out, rows,
                                   c1, cbase, c2corr, c3corr);
}

// round 9
// speedup vs baseline: 1.0224x; 1.0224x over previous
#include <cuda_runtime.h>

// LossFunction: fused IoU + smooth-L1 multi-loss over (B=256, N=8192, F=13).
//
// R9 = R8 footprint (4 blocks/SM x 104KB tile = 61MB in flight < L2 ->
// phase-2 L2 hits, traffic ~222MB confirmed in R8) x R6 warp count
// (256 thr x 4 blocks = 32 warps/SM -> 5.7-6.2 TB/s confirmed in R6/R7).
// LDG.256 streaming; 48KB smem pad is the occupancy governor.

#define F 13
#define THREADS 256
#define ROWS_TILE 1024
#define MAX_BLOCKS 4096
// v8 chunks per tile per tensor = 1024*13/8 = 1664 = 6*256 + 128

__device__ float        g_partials[MAX_BLOCKS];
__device__ unsigned int g_ticket = 0;

__device__ __forceinline__ float huber(float a, float b) {
    float d = fabsf(a - b);
    return d < 1.0f ? 0.5f * d * d : d - 0.5f;
}

__device__ __forceinline__ void ldg8(const float* p, float (&v)[8]) {
    unsigned r0, r1, r2, r3, r4, r5, r6, r7;
    asm("ld.global.nc.v8.b32 {%0,%1,%2,%3,%4,%5,%6,%7}, [%8];"
        : "=r"(r0), "=r"(r1), "=r"(r2), "=r"(r3),
          "=r"(r4), "=r"(r5), "=r"(r6), "=r"(r7)
        : "l"(p));
    v[0] = __uint_as_float(r0); v[1] = __uint_as_float(r1);
    v[2] = __uint_as_float(r2); v[3] = __uint_as_float(r3);
    v[4] = __uint_as_float(r4); v[5] = __uint_as_float(r5);
    v[6] = __uint_as_float(r6); v[7] = __uint_as_float(r7);
}

__global__ __launch_bounds__(THREADS)
void loss_kernel(const float* __restrict__ tg,
                 const float* __restrict__ pr,
                 float* __restrict__ out,
                 long long rows,
                 float c1, float cbase, float c2corr, float c3corr) {
    // Occupancy governor: 48KB static smem -> 4 blocks/SM (192KB of 228KB).
    // 4 x 256 threads = 32 warps/SM. First floats reused as reduction scratch.
    __shared__ float smem_pad[12288];  // 48 KB
    float* warp_part = smem_pad;       // THREADS/32 = 8 floats used
    __shared__ bool  is_last;

    long long row0 = (long long)blockIdx.x * ROWS_TILE;
    long long rem  = rows - row0;
    int nrows = rem < ROWS_TILE ? (int)rem : ROWS_TILE;

    const float* tbase = tg + row0 * F;
    const float* pbase = pr + row0 * F;

    // ---- Phase 1: uniform-weight streaming, LDG.256 ----
    float a0 = 0.0f, a1 = 0.0f, a2 = 0.0f, a3 = 0.0f;

    if (nrows == ROWS_TILE) {
        int idx = threadIdx.x;                 // v8-chunk index
        #pragma unroll
        for (int k = 0; k < 6; k++) {          // 6*256 = 1536 chunks
            float t[8], p[8];
            ldg8(tbase + idx * 8, t);
            ldg8(pbase + idx * 8, p);
            a0 += huber(t[0], p[0]) + huber(t[4], p[4]);
            a1 += huber(t[1], p[1]) + huber(t[5], p[5]);
            a2 += huber(t[2], p[2]) + huber(t[6], p[6]);
            a3 += huber(t[3], p[3]) + huber(t[7], p[7]);
            idx += THREADS;
        }
        if (threadIdx.x < 128) {               // tail chunks 1536..1663
            float t[8], p[8];
            ldg8(tbase + idx * 8, t);
            ldg8(pbase + idx * 8, p);
            a0 += huber(t[0], p[0]) + huber(t[4], p[4]);
            a1 += huber(t[1], p[1]) + huber(t[5], p[5]);
            a2 += huber(t[2], p[2]) + huber(t[6], p[6]);
            a3 += huber(t[3], p[3]) + huber(t[7], p[7]);
        }
    } else {
        int nflt = nrows * F;
        for (int i = threadIdx.x; i < nflt; i += THREADS)
            a0 += huber(__ldg(tbase + i), __ldg(pbase + i));
    }
    float acc = (a0 + a1 + a2 + a3) * cbase;

    // ---- Phase 2: per-row corrections + IoU; tile is L2-hot ----
    for (int r = threadIdx.x; r < nrows; r += THREADS) {
        const float* tr = tbase + r * F;
        const float* pq = pbase + r * F;
        float t0 = __ldg(tr + 0), t1 = __ldg(tr + 1);
        float t2 = __ldg(tr + 2), t3 = __ldg(tr + 3);
        float t12 = __ldg(tr + 12);
        float p0 = __ldg(pq + 0), p1 = __ldg(pq + 1);
        float p2 = __ldg(pq + 2), p3 = __ldg(pq + 3);
        float p12 = __ldg(pq + 12);

        float s2 = huber(t0, p0) + huber(t1, p1) + huber(t2, p2) + huber(t3, p3);
        acc += c2corr * s2;
        acc += c3corr * huber(t12, p12);

        float xx1 = fmaxf(t0, p0);
        float yy1 = fmaxf(t1, p1);
        float xx2 = fminf(t2, p2);
        float yy2 = fminf(t3, p3);
        float w = fmaxf(xx2 - xx1, 0.0f);
        float h = fmaxf(yy2 - yy1, 0.0f);
        float inter = w * h;
        float area1 = (t2 - t0) * (t3 - t1);
        float area2 = (p2 - p0) * (p3 - p1);
        float iou = inter / (area1 + area2 - inter + 1e-7f);
        acc += c1 * huber(1.0f, iou);
    }

    // ---- Block reduction ----
    #pragma unroll
    for (int off = 16; off > 0; off >>= 1)
        acc += __shfl_xor_sync(0xFFFFFFFFu, acc, off);

    int lane = threadIdx.x & 31;
    int wid  = threadIdx.x >> 5;
    if (lane == 0) warp_part[wid] = acc;
    __syncthreads();

    if (wid == 0) {
        float v = lane < (THREADS / 32) ? warp_part[lane] : 0.0f;
        #pragma unroll
        for (int off = 4; off > 0; off >>= 1)
            v += __shfl_xor_sync(0xFFFFFFFFu, v, off);
        if (lane == 0) {
            g_partials[blockIdx.x] = v;
            __threadfence();
            unsigned t = atomicAdd(&g_ticket, 1u);
            is_last = (t == gridDim.x - 1);
        }
    }
    __syncthreads();

    // Last block reduces all partials (deterministic order) and writes out.
    if (is_last) {
        __threadfence();
        float v = 0.0f;
        for (int i = threadIdx.x; i < (int)gridDim.x; i += THREADS)
            v += g_partials[i];
        #pragma unroll
        for (int off = 16; off > 0; off >>= 1)
            v += __shfl_xor_sync(0xFFFFFFFFu, v, off);
        if (lane == 0) warp_part[wid] = v;
        __syncthreads();
        if (wid == 0) {
            float s = lane < (THREADS / 32) ? warp_part[lane] : 0.0f;
            #pragma unroll
            for (int off = 4; off > 0; off >>= 1)
                s += __shfl_xor_sync(0xFFFFFFFFu, s, off);
            if (lane == 0) {
                out[0] = s;
                g_ticket = 0;   // reset for next graph replay
            }
        }
    }
}

extern "C" void kernel_launch(void* const* d_in, const int* in_sizes, int n_in,
                              void* d_out, int out_size) {
    const float* targets = (const float*)d_in[0];
    const float* preds   = (const float*)d_in[1];
    float* out = (float*)d_out;

    long long total = (long long)in_sizes[0];
    long long rows  = total / F;  // B*N = 2,097,152

    float inv = 1.0f / (float)rows;
    // Per-element weights: f<4: inv/4; 4<=f<12: inv/16; f==12: inv.
    float cbase  = inv * 0.0625f;
    float c2corr = inv * 0.25f - cbase;
    float c3corr = inv - cbase;
    float c1     = inv;

    int grid = (int)((rows + ROWS_TILE - 1) / ROWS_TILE);  // 2048
    if (grid > MAX_BLOCKS) grid = MAX_BLOCKS;  // safety (not hit for bench shape)

    loss_kernel<<<grid, THREADS>>>(targets, preds, out, rows,
                                   c1, cbase, c2corr, c3corr);
}

// round 10
// speedup vs baseline: 1.2814x; 1.2534x over previous
#include <cuda_runtime.h>

// LossFunction: fused IoU + smooth-L1 multi-loss over (B=256, N=8192, F=13).
//
// R10: SINGLE-PASS. Each thread owns 4 consecutive rows = 52 floats =
// 13 aligned float4 per tensor. Feature identity of every loaded component
// is compile-time static (g=4c+j -> r=g/13, f=g%13 const-folded), so exact
// per-feature weights are applied inline and the 10 IoU features per thread
// are captured to registers. No second phase, no smem staging, every byte
// read from DRAM exactly once -> DRAM busy for the whole kernel.
// (R9 lesson: two-phase structure idles DRAM during L2-served phase 2.)

#define F 13
#define THREADS 256
#define ROWS_PER_THREAD 4
#define ROWS_TILE (THREADS * ROWS_PER_THREAD)   // 1024
#define MAX_BLOCKS 4096

__device__ float        g_partials[MAX_BLOCKS];
__device__ unsigned int g_ticket = 0;

__device__ __forceinline__ float huber(float a, float b) {
    float d = fabsf(a - b);
    return d < 1.0f ? 0.5f * d * d : d - 0.5f;
}

__global__ __launch_bounds__(THREADS, 3)
void loss_kernel(const float* __restrict__ tg,
                 const float* __restrict__ pr,
                 float* __restrict__ out,
                 long long rows,
                 float c1, float w2, float w4, float w3) {
    long long tile0 = (long long)blockIdx.x * ROWS_TILE;
    long long rem   = rows - tile0;
    int nrows = rem < ROWS_TILE ? (int)rem : ROWS_TILE;

    float acc = 0.0f;

    if (nrows == ROWS_TILE) {
        // Thread t owns rows tile0 + 4t .. 4t+3 : 52 floats = 13 float4 (16B aligned).
        long long r0 = tile0 + (long long)threadIdx.x * ROWS_PER_THREAD;
        const float4* t4 = (const float4*)(tg + r0 * F);
        const float4* p4 = (const float4*)(pr + r0 * F);

        float tb[ROWS_PER_THREAD][4], pb[ROWS_PER_THREAD][4];
        float tl[ROWS_PER_THREAD],    pl[ROWS_PER_THREAD];

        float a0 = 0.0f, a1 = 0.0f;
        #pragma unroll
        for (int c = 0; c < 13; c++) {
            float4 tv = __ldg(t4 + c);
            float4 pv = __ldg(p4 + c);
            float ta[4] = {tv.x, tv.y, tv.z, tv.w};
            float pa[4] = {pv.x, pv.y, pv.z, pv.w};
            #pragma unroll
            for (int j = 0; j < 4; j++) {
                const int g = 4 * c + j;        // 0..51, compile-time
                const int r = g / 13;           // row within thread
                const int f = g - 13 * r;       // feature index
                float wgt = (f < 4) ? w2 : ((f < 12) ? w4 : w3);
                if (j & 1) a1 += wgt * huber(ta[j], pa[j]);
                else       a0 += wgt * huber(ta[j], pa[j]);
                if (f < 4)   { tb[r][f] = ta[j]; pb[r][f] = pa[j]; }
                if (f == 12) { tl[r]    = ta[j]; pl[r]    = pa[j]; }
            }
        }
        acc = a0 + a1;

        // IoU loss for the 4 owned rows (all operands in registers).
        #pragma unroll
        for (int r = 0; r < ROWS_PER_THREAD; r++) {
            float xx1 = fmaxf(tb[r][0], pb[r][0]);
            float yy1 = fmaxf(tb[r][1], pb[r][1]);
            float xx2 = fminf(tb[r][2], pb[r][2]);
            float yy2 = fminf(tb[r][3], pb[r][3]);
            float w = fmaxf(xx2 - xx1, 0.0f);
            float h = fmaxf(yy2 - yy1, 0.0f);
            float inter = w * h;
            float area1 = (tb[r][2] - tb[r][0]) * (tb[r][3] - tb[r][1]);
            float area2 = (pb[r][2] - pb[r][0]) * (pb[r][3] - pb[r][1]);
            float iou = inter / (area1 + area2 - inter + 1e-7f);
            acc += c1 * huber(1.0f, iou);
        }
        (void)tl; (void)pl;  // f12 already weighted in the sweep
    } else {
        // Generic tail tile (not hit for the benchmark shape).
        for (int r = threadIdx.x; r < nrows; r += THREADS) {
            const float* tr = tg + (tile0 + r) * F;
            const float* pq = pr + (tile0 + r) * F;
            float t[F], p[F];
            #pragma unroll
            for (int f = 0; f < F; f++) { t[f] = __ldg(tr + f); p[f] = __ldg(pq + f); }
            #pragma unroll
            for (int f = 0; f < F; f++) {
                float wgt = (f < 4) ? w2 : ((f < 12) ? w4 : w3);
                acc += wgt * huber(t[f], p[f]);
            }
            float xx1 = fmaxf(t[0], p[0]);
            float yy1 = fmaxf(t[1], p[1]);
            float xx2 = fminf(t[2], p[2]);
            float yy2 = fminf(t[3], p[3]);
            float w = fmaxf(xx2 - xx1, 0.0f);
            float h = fmaxf(yy2 - yy1, 0.0f);
            float inter = w * h;
            float area1 = (t[2] - t[0]) * (t[3] - t[1]);
            float area2 = (p[2] - p[0]) * (p[3] - p[1]);
            float iou = inter / (area1 + area2 - inter + 1e-7f);
            acc += c1 * huber(1.0f, iou);
        }
    }

    // ---- Block reduction ----
    #pragma unroll
    for (int off = 16; off > 0; off >>= 1)
        acc += __shfl_xor_sync(0xFFFFFFFFu, acc, off);

    __shared__ float warp_part[THREADS / 32];
    __shared__ bool  is_last;
    int lane = threadIdx.x & 31;
    int wid  = threadIdx.x >> 5;
    if (lane == 0) warp_part[wid] = acc;
    __syncthreads();

    if (wid == 0) {
        float v = lane < (THREADS / 32) ? warp_part[lane] : 0.0f;
        #pragma unroll
        for (int off = 4; off > 0; off >>= 1)
            v += __shfl_xor_sync(0xFFFFFFFFu, v, off);
        if (lane == 0) {
            g_partials[blockIdx.x] = v;
            __threadfence();
            unsigned t = atomicAdd(&g_ticket, 1u);
            is_last = (t == gridDim.x - 1);
        }
    }
    __syncthreads();

    // Last block reduces all partials (deterministic order) and writes out.
    if (is_last) {
        __threadfence();
        float v = 0.0f;
        for (int i = threadIdx.x; i < (int)gridDim.x; i += THREADS)
            v += g_partials[i];
        #pragma unroll
        for (int off = 16; off > 0; off >>= 1)
            v += __shfl_xor_sync(0xFFFFFFFFu, v, off);
        if (lane == 0) warp_part[wid] = v;
        __syncthreads();
        if (wid == 0) {
            float s = lane < (THREADS / 32) ? warp_part[lane] : 0.0f;
            #pragma unroll
            for (int off = 4; off > 0; off >>= 1)
                s += __shfl_xor_sync(0xFFFFFFFFu, s, off);
            if (lane == 0) {
                out[0] = s;
                g_ticket = 0;   // reset for next graph replay
            }
        }
    }
}

extern "C" void kernel_launch(void* const* d_in, const int* in_sizes, int n_in,
                              void* d_out, int out_size) {
    const float* targets = (const float*)d_in[0];
    const float* preds   = (const float*)d_in[1];
    float* out = (float*)d_out;

    long long total = (long long)in_sizes[0];
    long long rows  = total / F;  // B*N = 2,097,152

    float inv = 1.0f / (float)rows;
    // Exact per-feature weights (no algebraic split needed — selection is static):
    float w2 = inv * 0.25f;    // f in [0,4)  : loss2 mean over rows*4
    float w4 = inv * 0.0625f;  // f in [4,12) : 0.5 * mean over rows*8
    float w3 = inv;            // f == 12     : loss3 mean over rows
    float c1 = inv;            // loss1 mean

    int grid = (int)((rows + ROWS_TILE - 1) / ROWS_TILE);  // 2048
    if (grid > MAX_BLOCKS) grid = MAX_BLOCKS;  // safety (not hit for bench shape)

    loss_kernel<<<grid, THREADS>>>(targets, preds, out, rows, c1, w2, w4, w3);
}